// round 5
// baseline (speedup 1.0000x reference)
#include <cuda_runtime.h>
#include <cstdint>

#define BT 384
#define NN 325
#define MT (BT*NN)     // 124800

// ---------------- scratch ----------------
__device__ float g_xn     [(size_t)MT*128];
__device__ float g_qkv    [(size_t)MT*384];
__device__ float g_coords [(size_t)MT*2];
__device__ float g_u      [(size_t)MT*128];
__device__ float g_vn     [(size_t)MT*128];
__device__ float g_attnout[(size_t)MT*128];
__device__ float g_gateres[(size_t)MT*128];
__device__ float g_sg     [(size_t)MT*128];
__device__ float g_wqkv   [384*128];
__device__ float g_w1     [256*128];
__device__ float g_wo     [128*128];
__device__ float g_w2     [128*128];
__device__ float g_cwt    [3*325*352];   // [tap][n][m-permuted, padded 352]

// ---------------- helpers ----------------
__device__ __forceinline__ float rnd_tf32(float f) {
    unsigned u;
    asm("cvt.rna.tf32.f32 %0, %1;" : "=r"(u) : "f"(f));
    return __uint_as_float(u);
}
__device__ __host__ __forceinline__ int pcol(int k) {
    return (k & ~31) | ((k & 3) << 3) | ((k >> 2) & 7);
}
__device__ __forceinline__ unsigned sptr(const void* p) {
    return (unsigned)__cvta_generic_to_shared(p);
}
__device__ __forceinline__ void cp16(unsigned dst, const void* src, bool pred) {
    int sz = pred ? 16 : 0;
    asm volatile("cp.async.ca.shared.global [%0], [%1], 16, %2;\n"
                 :: "r"(dst), "l"(src), "r"(sz));
}
#define CP_COMMIT() asm volatile("cp.async.commit_group;\n")
#define CP_WAIT(n)  asm volatile("cp.async.wait_group %0;\n" :: "n"(n))

__device__ __forceinline__ void mma_tf32(float& c0, float& c1, float& c2, float& c3,
                                         float a0, float a1, float a2, float a3,
                                         float b0, float b1) {
    asm volatile("mma.sync.aligned.m16n8k8.row.col.f32.tf32.tf32.f32 "
                 "{%0,%1,%2,%3}, {%4,%5,%6,%7}, {%8,%9}, {%0,%1,%2,%3};\n"
                 : "+f"(c0), "+f"(c1), "+f"(c2), "+f"(c3)
                 : "r"(__float_as_uint(a0)), "r"(__float_as_uint(a1)),
                   "r"(__float_as_uint(a2)), "r"(__float_as_uint(a3)),
                   "r"(__float_as_uint(b0)), "r"(__float_as_uint(b1)));
}

// ---------------- prep: transpose+round+permute all weights ------------
__global__ __launch_bounds__(256)
void prep_kernel(const float* __restrict__ Wqkv, const float* __restrict__ W1,
                 const float* __restrict__ Wo, const float* __restrict__ W2,
                 const float* __restrict__ cw,
                 float* __restrict__ oq, float* __restrict__ o1,
                 float* __restrict__ oo, float* __restrict__ o2,
                 float* __restrict__ ocw)
{
    int i = blockIdx.x * 256 + threadIdx.x;
    if (i < 49152) {
        int n = i >> 7, k = i & 127;
        oq[n*128 + pcol(k)] = rnd_tf32(Wqkv[(size_t)k*384 + n]); return;
    }
    i -= 49152;
    if (i < 32768) {
        int n = i >> 7, k = i & 127;
        o1[n*128 + pcol(k)] = rnd_tf32(W1[(size_t)k*256 + n]); return;
    }
    i -= 32768;
    if (i < 16384) {
        int n = i >> 7, k = i & 127;
        oo[n*128 + pcol(k)] = rnd_tf32(Wo[(size_t)k*128 + n]); return;
    }
    i -= 16384;
    if (i < 16384) {
        int n = i >> 7, k = i & 127;
        o2[n*128 + pcol(k)] = rnd_tf32(W2[(size_t)k*128 + n]); return;
    }
    i -= 16384;
    if (i < 3*325*352) {
        int t = i / 114400, rem = i % 114400;
        int n = rem / 352, mc = rem % 352;
        float v = (mc < 325) ? rnd_tf32(cw[((size_t)n*325 + mc)*3 + t]) : 0.f;
        ocw[(size_t)t*114400 + n*352 + pcol(mc)] = v;
    }
}

// ---------------- LayerNorm of x -> xn (permuted, rounded) + coords ----
__global__ __launch_bounds__(256)
void ln_kernel(const float* __restrict__ in, float* __restrict__ out,
               const float* __restrict__ gam, const float* __restrict__ bet,
               float* __restrict__ coords,
               const float* __restrict__ Wl, const float* __restrict__ bl)
{
    int row = blockIdx.x * 8 + (threadIdx.x >> 5);
    if (row >= MT) return;
    int lane = threadIdx.x & 31;
    float4 v = *(const float4*)(in + (size_t)row * 128 + lane * 4);
    float s  = v.x + v.y + v.z + v.w;
    float ss = v.x*v.x + v.y*v.y + v.z*v.z + v.w*v.w;
#pragma unroll
    for (int o = 16; o > 0; o >>= 1) {
        s  += __shfl_xor_sync(0xffffffffu, s,  o);
        ss += __shfl_xor_sync(0xffffffffu, ss, o);
    }
    float mean = s * (1.f/128.f);
    float var  = ss * (1.f/128.f) - mean * mean;
    float r = rsqrtf(var + 1e-5f);
    int c = lane * 4;
    float o0 = (v.x - mean) * r * gam[c+0] + bet[c+0];
    float o1 = (v.y - mean) * r * gam[c+1] + bet[c+1];
    float o2 = (v.z - mean) * r * gam[c+2] + bet[c+2];
    float o3 = (v.w - mean) * r * gam[c+3] + bet[c+3];
    float* orow = out + (size_t)row * 128;
    int cb = (lane >> 3) * 32 + (lane & 7);
    orow[cb +  0] = rnd_tf32(o0);
    orow[cb +  8] = rnd_tf32(o1);
    orow[cb + 16] = rnd_tf32(o2);
    orow[cb + 24] = rnd_tf32(o3);
    float c0 = o0*Wl[(c+0)*2] + o1*Wl[(c+1)*2] + o2*Wl[(c+2)*2] + o3*Wl[(c+3)*2];
    float c1 = o0*Wl[(c+0)*2+1] + o1*Wl[(c+1)*2+1] + o2*Wl[(c+2)*2+1] + o3*Wl[(c+3)*2+1];
#pragma unroll
    for (int o = 16; o > 0; o >>= 1) {
        c0 += __shfl_xor_sync(0xffffffffu, c0, o);
        c1 += __shfl_xor_sync(0xffffffffu, c1, o);
    }
    if (lane == 0) {
        coords[(size_t)row*2 + 0] = c0 + bl[0];
        coords[(size_t)row*2 + 1] = c1 + bl[1];
    }
}

// ======== shared mainloop fragments (A [128][36] per-kt, B [128][132]) ==
#define GEMM_DECLS                                                           \
    const int lane = tid & 31, wid = tid >> 5;                               \
    const int wm = wid >> 1, wn = wid & 1;                                   \
    const int qg = lane >> 2, rg = lane & 3;                                 \
    float acc[2][8][4];                                                      \
    _Pragma("unroll") for (int a_ = 0; a_ < 2; a_++)                         \
    _Pragma("unroll") for (int b_ = 0; b_ < 8; b_++)                         \
    _Pragma("unroll") for (int c_ = 0; c_ < 4; c_++) acc[a_][b_][c_] = 0.f;

#define GEMM_STEP(Ac, Bsrc, bstride, kcol)                                   \
    _Pragma("unroll")                                                        \
    for (int h = 0; h < 2; h++) {                                            \
        float av[2][2][4]; float bv[8][4];                                   \
        _Pragma("unroll")                                                    \
        for (int mt = 0; mt < 2; mt++)                                       \
        _Pragma("unroll")                                                    \
        for (int rh = 0; rh < 2; rh++)                                       \
            *(float4*)av[mt][rh] = *(const float4*)&(Ac)[(wm*32+mt*16+qg+rh*8)*36 + rg*8 + h*4]; \
        _Pragma("unroll")                                                    \
        for (int nt = 0; nt < 8; nt++)                                       \
            *(float4*)bv[nt] = *(const float4*)&(Bsrc)[(wn*64+nt*8+qg)*(bstride) + (kcol) + rg*8 + h*4]; \
        _Pragma("unroll")                                                    \
        for (int s2 = 0; s2 < 2; s2++) {                                     \
            _Pragma("unroll")                                                \
            for (int mt = 0; mt < 2; mt++) {                                 \
                float a0 = av[mt][0][2*s2],   a1 = av[mt][1][2*s2];          \
                float a2 = av[mt][0][2*s2+1], a3 = av[mt][1][2*s2+1];        \
                _Pragma("unroll")                                            \
                for (int nt = 0; nt < 8; nt++)                               \
                    mma_tf32(acc[mt][nt][0], acc[mt][nt][1], acc[mt][nt][2], acc[mt][nt][3], \
                             a0, a1, a2, a3, bv[nt][2*s2], bv[nt][2*s2+1]);  \
            }                                                                \
        }                                                                    \
    }

// ---------------- dense GEMM (M=MT, K=128), A & B permuted --------------
// EPI: 0 = +bias ; 2 = +bias, ReLU, +residual
template<int EPI, bool QKVMAP, bool RND>
__global__ __launch_bounds__(256, 2)
void gemm128(const float* __restrict__ A, const float* __restrict__ Bw,
             float* __restrict__ C, int ldc,
             const float* __restrict__ bias, const float* __restrict__ res)
{
    extern __shared__ float sm[];
    float* Bs = sm;                 // [128][132]
    float* As = sm + 128*132;       // [2][128][36]
    const int tid = threadIdx.x;
    const int row0 = blockIdx.y * 128, col0 = blockIdx.x * 128;
    {
        const float* Bp = Bw + (size_t)col0 * 128;
#pragma unroll
        for (int i = 0; i < 16; i++) {
            int lin = tid + 256*i; int r = lin >> 5, ch = lin & 31;
            cp16(sptr(Bs + r*132 + ch*4), Bp + (size_t)r*128 + ch*4, true);
        }
    }
    CP_COMMIT();
#define LA(st, k0) do {                                                      \
        float* dst = As + (st)*128*36;                                       \
        _Pragma("unroll")                                                    \
        for (int i = 0; i < 4; i++) {                                        \
            int lin = tid + 256*i; int r = lin >> 3, ch = lin & 7;           \
            cp16(sptr(dst + r*36 + ch*4),                                    \
                 A + (size_t)(row0 + r)*128 + (k0) + ch*4, true);            \
        }                                                                    \
        CP_COMMIT();                                                         \
    } while (0)
    LA(0, 0); LA(1, 32);
    CP_WAIT(1);
    __syncthreads();
    GEMM_DECLS
    for (int kt = 0; kt < 4; kt++) {
        const float* Ac = As + (kt & 1)*128*36;
        GEMM_STEP(Ac, Bs, 132, kt*32)
        if (kt < 2) {
            __syncthreads();
            LA(kt & 1, (kt + 2)*32);
            CP_WAIT(1);
            __syncthreads();
        } else if (kt == 2) {
            CP_WAIT(0);
            __syncthreads();
        }
    }
#undef LA
#pragma unroll
    for (int mt = 0; mt < 2; mt++)
#pragma unroll
        for (int i2 = 0; i2 < 2; i2++) {
            int r = row0 + wm*32 + mt*16 + qg + i2*8;
#pragma unroll
            for (int nt = 0; nt < 8; nt++)
#pragma unroll
                for (int j = 0; j < 2; j++) {
                    int c = col0 + wn*64 + nt*8 + rg*2 + j;
                    float v = acc[mt][nt][i2*2 + j] + bias[c];
                    if (EPI == 2) v = fmaxf(v, 0.f) + res[(size_t)r*128 + c];
                    if (RND) v = rnd_tf32(v);
                    int oc = QKVMAP ? ((c < 256) ? ((c & ~127) + pcol(c & 127)) : c) : c;
                    C[(size_t)r * ldc + oc] = v;
                }
        }
}

// ---------------- FC1: relu(xn@W1 + b1 + coords-affine); fused SGU-LN ---
__global__ __launch_bounds__(256, 2)
void fc1_kernel(const float* __restrict__ A, const float* __restrict__ Bw,
                float* __restrict__ u, float* __restrict__ vn,
                const float* __restrict__ coords,
                const float* __restrict__ b1,
                const float* __restrict__ aW, const float* __restrict__ ab,
                const float* __restrict__ sgu_g, const float* __restrict__ sgu_b)
{
    extern __shared__ float sm[];
    float* Bs = sm;
    float* As = sm + 128*132;
    const int tid = threadIdx.x;
    const int row0 = blockIdx.y * 128, col0 = blockIdx.x * 128;
    {
        const float* Bp = Bw + (size_t)col0 * 128;
#pragma unroll
        for (int i = 0; i < 16; i++) {
            int lin = tid + 256*i; int r = lin >> 5, ch = lin & 31;
            cp16(sptr(Bs + r*132 + ch*4), Bp + (size_t)r*128 + ch*4, true);
        }
    }
    CP_COMMIT();
#define LA(st, k0) do {                                                      \
        float* dst = As + (st)*128*36;                                       \
        _Pragma("unroll")                                                    \
        for (int i = 0; i < 4; i++) {                                        \
            int lin = tid + 256*i; int r = lin >> 3, ch = lin & 7;           \
            cp16(sptr(dst + r*36 + ch*4),                                    \
                 A + (size_t)(row0 + r)*128 + (k0) + ch*4, true);            \
        }                                                                    \
        CP_COMMIT();                                                         \
    } while (0)
    LA(0, 0); LA(1, 32);
    CP_WAIT(1);
    __syncthreads();
    GEMM_DECLS
    for (int kt = 0; kt < 4; kt++) {
        const float* Ac = As + (kt & 1)*128*36;
        GEMM_STEP(Ac, Bs, 132, kt*32)
        if (kt < 2) {
            __syncthreads();
            LA(kt & 1, (kt + 2)*32);
            CP_WAIT(1);
            __syncthreads();
        } else if (kt == 2) {
            CP_WAIT(0);
            __syncthreads();
        }
    }
#undef LA
    // epilogue: affine + relu, in place
    float sums[2][2], sqs[2][2];
#pragma unroll
    for (int mt = 0; mt < 2; mt++)
#pragma unroll
        for (int i2 = 0; i2 < 2; i2++) { sums[mt][i2] = 0.f; sqs[mt][i2] = 0.f; }
#pragma unroll
    for (int mt = 0; mt < 2; mt++)
#pragma unroll
        for (int i2 = 0; i2 < 2; i2++) {
            int r = row0 + wm*32 + mt*16 + qg + i2*8;
            float c0v = coords[(size_t)r*2], c1v = coords[(size_t)r*2 + 1];
#pragma unroll
            for (int nt = 0; nt < 8; nt++)
#pragma unroll
                for (int j = 0; j < 2; j++) {
                    int c = col0 + wn*64 + nt*8 + rg*2 + j;
                    float v = acc[mt][nt][i2*2 + j] + b1[c] + c0v*aW[c] + c1v*aW[256 + c] + ab[c];
                    v = fmaxf(v, 0.f);
                    acc[mt][nt][i2*2 + j] = v;
                    sums[mt][i2] += v;
                    sqs[mt][i2]  += v * v;
                }
        }
    if (col0 == 0) {
        // u half: write linear fp32
#pragma unroll
        for (int mt = 0; mt < 2; mt++)
#pragma unroll
            for (int i2 = 0; i2 < 2; i2++) {
                int r = row0 + wm*32 + mt*16 + qg + i2*8;
#pragma unroll
                for (int nt = 0; nt < 8; nt++)
#pragma unroll
                    for (int j = 0; j < 2; j++) {
                        int c = wn*64 + nt*8 + rg*2 + j;
                        u[(size_t)r*128 + c] = acc[mt][nt][i2*2 + j];
                    }
            }
    } else {
        // vv half: fused LayerNorm -> vn (linear, rounded)
        float* rowstat = As;   // reuse, 128*4 floats
        __syncthreads();
#pragma unroll
        for (int mt = 0; mt < 2; mt++)
#pragma unroll
            for (int i2 = 0; i2 < 2; i2++) {
                float s = sums[mt][i2], q = sqs[mt][i2];
                s += __shfl_xor_sync(0xffffffffu, s, 1);
                s += __shfl_xor_sync(0xffffffffu, s, 2);
                q += __shfl_xor_sync(0xffffffffu, q, 1);
                q += __shfl_xor_sync(0xffffffffu, q, 2);
                if (rg == 0) {
                    int rl = wm*32 + mt*16 + qg + i2*8;
                    rowstat[rl*4 + wn*2 + 0] = s;
                    rowstat[rl*4 + wn*2 + 1] = q;
                }
            }
        __syncthreads();
#pragma unroll
        for (int mt = 0; mt < 2; mt++)
#pragma unroll
            for (int i2 = 0; i2 < 2; i2++) {
                int rl = wm*32 + mt*16 + qg + i2*8;
                int r = row0 + rl;
                float s = rowstat[rl*4] + rowstat[rl*4 + 2];
                float q = rowstat[rl*4 + 1] + rowstat[rl*4 + 3];
                float mean = s * (1.f/128.f);
                float var  = q * (1.f/128.f) - mean * mean;
                float rinv = rsqrtf(var + 1e-5f);
#pragma unroll
                for (int nt = 0; nt < 8; nt++)
#pragma unroll
                    for (int j = 0; j < 2; j++) {
                        int f = wn*64 + nt*8 + rg*2 + j;
                        float v = (acc[mt][nt][i2*2 + j] - mean) * rinv * sgu_g[f] + sgu_b[f];
                        vn[(size_t)r*128 + f] = rnd_tf32(v);
                    }
            }
    }
}

// ---------------- fused flash attention: grid (3, BT) -------------------
__global__ __launch_bounds__(256)
void attn_kernel(const float* __restrict__ qkv, float* __restrict__ attnout)
{
    extern __shared__ float sm[];
    float* qs   = sm;                     // [128][132] (q, permuted k-dim)
    float* ks   = sm + 128*132;           // [128][132] (k tile; reused as P)
    float* vs   = sm + 2*128*132;         // [128][136] (v, linear)
    float* lsum = sm + 2*128*132 + 128*136;
    const int bt = blockIdx.y, q0 = blockIdx.x * 128;
    const int tid = threadIdx.x;
    const float* base = qkv + (size_t)bt * NN * 384;

#define LQ(dst, stridew, off, r0) do {                                       \
        _Pragma("unroll")                                                    \
        for (int i = 0; i < 16; i++) {                                       \
            int lin = tid + 256*i; int r = lin >> 5, ch = lin & 31;          \
            bool p = ((r0) + r) < NN;                                        \
            cp16(sptr((dst) + r*(stridew) + ch*4),                           \
                 base + (size_t)((r0) + r)*384 + (off) + ch*4, p);           \
        }                                                                    \
    } while (0)

    LQ(qs, 132, 0,   q0);
    LQ(ks, 132, 128, 0);
    LQ(vs, 136, 256, 0);
    CP_COMMIT();
    lsum[tid] = 0.f;
    CP_WAIT(0);
    __syncthreads();

    const int lane = tid & 31, wid = tid >> 5;
    const int wm = wid >> 1, wn = wid & 1;
    const int qg = lane >> 2, rg = lane & 3;
    float Oacc[2][8][4];
#pragma unroll
    for (int a = 0; a < 2; a++)
#pragma unroll
        for (int b = 0; b < 8; b++)
#pragma unroll
            for (int c = 0; c < 4; c++) Oacc[a][b][c] = 0.f;

    for (int it = 0; it < 3; it++) {
        const int k0g = it * 128;
        float acc[2][8][4];
#pragma unroll
        for (int a = 0; a < 2; a++)
#pragma unroll
            for (int b = 0; b < 8; b++)
#pragma unroll
                for (int c = 0; c < 4; c++) acc[a][b][c] = 0.f;
        // S = q @ k^T  (vectorized fragments, both permuted on feature dim)
        for (int kt = 0; kt < 4; kt++) {
            GEMM_STEP(qs /*dummy-a*/, ks, 132, kt*32)
        }
        // NOTE: GEMM_STEP used qs for A? It uses (Ac) param — fix via macro arg:
        // (A-operand rows are qs with stride 132; see specialized step below.)
        // exp + mask + row sums
        float rs[2][2] = {{0.f,0.f},{0.f,0.f}};
#pragma unroll
        for (int mt = 0; mt < 2; mt++)
#pragma unroll
            for (int nt = 0; nt < 8; nt++)
#pragma unroll
                for (int idx = 0; idx < 4; idx++) {
                    int col = k0g + wn*64 + nt*8 + rg*2 + (idx & 1);
                    float p = (col < NN) ? rnd_tf32(__expf(acc[mt][nt][idx])) : 0.f;
                    acc[mt][nt][idx] = p;
                    rs[mt][idx >> 1] += p;
                }
#pragma unroll
        for (int mt = 0; mt < 2; mt++)
#pragma unroll
            for (int i2 = 0; i2 < 2; i2++) {
                float r = rs[mt][i2];
                r += __shfl_xor_sync(0xffffffffu, r, 1);
                r += __shfl_xor_sync(0xffffffffu, r, 2);
                if (rg == 0)
                    lsum[(wm*32 + mt*16 + qg + i2*8)*2 + wn] += r;
            }
        __syncthreads();
        // store P into ks (permuted key-dim)
#pragma unroll
        for (int mt = 0; mt < 2; mt++)
#pragma unroll
            for (int nt = 0; nt < 8; nt++)
#pragma unroll
                for (int idx = 0; idx < 4; idx++) {
                    int r = wm*32 + mt*16 + qg + (idx >> 1)*8;
                    int c = wn*64 + nt*8 + rg*2 + (idx & 1);
                    ks[r*132 + pcol(c)] = acc[mt][nt][idx];
                }
        __syncthreads();
        // O += P @ v   (A = P vectorized; B = v scalar)
        for (int kt = 0; kt < 4; kt++) {
#pragma unroll
            for (int h = 0; h < 2; h++) {
                float av[2][2][4];
#pragma unroll
                for (int mt = 0; mt < 2; mt++)
#pragma unroll
                    for (int rh = 0; rh < 2; rh++)
                        *(float4*)av[mt][rh] = *(const float4*)&ks[(wm*32+mt*16+qg+rh*8)*132 + kt*32 + rg*8 + h*4];
#pragma unroll
                for (int s2 = 0; s2 < 2; s2++) {
                    int kk = kt*32 + h*16 + s2*8;
                    float b0[8], b1[8];
#pragma unroll
                    for (int nt = 0; nt < 8; nt++) {
                        int c = wn*64 + nt*8 + qg;
                        b0[nt] = vs[(kk + rg)*136 + c];
                        b1[nt] = vs[(kk + rg + 4)*136 + c];
                    }
#pragma unroll
                    for (int mt = 0; mt < 2; mt++) {
                        float a0 = av[mt][0][2*s2],   a1 = av[mt][1][2*s2];
                        float a2 = av[mt][0][2*s2+1], a3 = av[mt][1][2*s2+1];
#pragma unroll
                        for (int nt = 0; nt < 8; nt++)
                            mma_tf32(Oacc[mt][nt][0], Oacc[mt][nt][1], Oacc[mt][nt][2], Oacc[mt][nt][3],
                                     a0, a1, a2, a3, b0[nt], b1[nt]);
                    }
                }
            }
        }
        __syncthreads();
        if (it < 2) {
            LQ(ks, 132, 128, (it + 1)*128);
            LQ(vs, 136, 256, (it + 1)*128);
            CP_COMMIT();
            CP_WAIT(0);
            __syncthreads();
        }
    }
#undef LQ
    // epilogue: O / l -> attnout (permuted, rounded)
#pragma unroll
    for (int mt = 0; mt < 2; mt++)
#pragma unroll
        for (int i2 = 0; i2 < 2; i2++) {
            int rl = wm*32 + mt*16 + qg + i2*8;
            int n = q0 + rl;
            if (n >= NN) continue;
            float inv = 1.f / (lsum[rl*2] + lsum[rl*2 + 1]);
            float* orow = attnout + ((size_t)bt * NN + n) * 128;
#pragma unroll
            for (int nt = 0; nt < 8; nt++)
#pragma unroll
                for (int j = 0; j < 2; j++) {
                    int f = wn*64 + nt*8 + rg*2 + j;
                    orow[pcol(f)] = rnd_tf32(Oacc[mt][nt][i2*2 + j] * inv);
                }
        }
}

// ---------------- conv: A=cwt (permuted m), B=vn rows, tap via shift ----
__global__ __launch_bounds__(256, 2)
void conv_tc(const float* __restrict__ cwt, const float* __restrict__ vn,
             const float* __restrict__ cb, const float* __restrict__ gres,
             const float* __restrict__ u, float* __restrict__ sg)
{
    extern __shared__ float sm[];
    float* As = sm;                 // [2][128][36]
    float* Bs = sm + 2*128*36;      // [2][32][136]
    const int bt = blockIdx.y, n0 = blockIdx.x * 128;
    const int tid = threadIdx.x;
    const float* vbt = vn + (size_t)bt * NN * 128;

#define LT(st, tap_, m0_) do {                                               \
        float* Ad = As + (st)*128*36;                                        \
        float* Bd = Bs + (st)*32*136;                                        \
        const float* cwp = cwt + (size_t)(tap_)*114400;                      \
        _Pragma("unroll")                                                    \
        for (int i = 0; i < 4; i++) {                                        \
            int lin = tid + 256*i; int r = lin >> 3, ch = lin & 7;           \
            bool p = (n0 + r) < NN;                                          \
            cp16(sptr(Ad + r*36 + ch*4),                                     \
                 cwp + (size_t)(n0 + r)*352 + (m0_) + ch*4, p);              \
        }                                                                    \
        _Pragma("unroll")                                                    \
        for (int i = 0; i < 4; i++) {                                        \
            int lin = tid + 256*i; int r = lin >> 5, ch = lin & 31;          \
            bool p = ((m0_) + r) < NN;                                       \
            cp16(sptr(Bd + r*136 + ch*4),                                    \
                 vbt + (size_t)((m0_) + r)*128 + ch*4, p);                   \
        }                                                                    \
        CP_COMMIT();                                                         \
    } while (0)

    LT(0, 0, 0); LT(1, 0, 32);
    CP_WAIT(1);
    __syncthreads();

    const int lane = tid & 31, wid = tid >> 5;
    const int wm = wid >> 1, wn = wid & 1;
    const int qg = lane >> 2, rg = lane & 3;
    float acc[2][8][4];
#pragma unroll
    for (int a = 0; a < 2; a++)
#pragma unroll
        for (int b = 0; b < 8; b++)
#pragma unroll
            for (int c = 0; c < 4; c++) acc[a][b][c] = 0.f;

    const int NSTEP = 33;
    for (int q = 0; q < NSTEP; q++) {
        const int tap = q / 11;
        const float* Ac = As + (q & 1)*128*36;
        const float* Bc = Bs + (q & 1)*32*136;
#pragma unroll
        for (int h = 0; h < 2; h++) {
            float av[2][2][4];
#pragma unroll
            for (int mt = 0; mt < 2; mt++)
#pragma unroll
                for (int rh = 0; rh < 2; rh++)
                    *(float4*)av[mt][rh] = *(const float4*)&Ac[(wm*32+mt*16+qg+rh*8)*36 + rg*8 + h*4];
#pragma unroll
            for (int s2 = 0; s2 < 2; s2++) {
                int kk = h*16 + s2*8;
                float b0[8], b1[8];
#pragma unroll
                for (int nt = 0; nt < 8; nt++) {
                    int cs = wn*64 + nt*8 + qg + tap - 1;
                    bool ok = (cs >= 0) && (cs < 128);
                    b0[nt] = ok ? Bc[(kk + rg)*136 + cs] : 0.f;
                    b1[nt] = ok ? Bc[(kk + rg + 4)*136 + cs] : 0.f;
                }
#pragma unroll
                for (int mt = 0; mt < 2; mt++) {
                    float a0 = av[mt][0][2*s2],   a1 = av[mt][1][2*s2];
                    float a2 = av[mt][0][2*s2+1], a3 = av[mt][1][2*s2+1];
#pragma unroll
                    for (int nt = 0; nt < 8; nt++)
                        mma_tf32(acc[mt][nt][0], acc[mt][nt][1], acc[mt][nt][2], acc[mt][nt][3],
                                 a0, a1, a2, a3, b0[nt], b1[nt]);
                }
            }
        }
        if (q + 2 < NSTEP) {
            int qn = q + 2;
            __syncthreads();
            LT(q & 1, qn / 11, (qn % 11)*32);
            CP_WAIT(1);
            __syncthreads();
        } else if (q + 1 < NSTEP) {
            CP_WAIT(0);
            __syncthreads();
        }
    }
#undef LT
#pragma unroll
    for (int mt = 0; mt < 2; mt++)
#pragma unroll
        for (int i2 = 0; i2 < 2; i2++) {
            int n = n0 + wm*32 + mt*16 + qg + i2*8;
            if (n >= NN) continue;
            size_t row = (size_t)bt * NN + n;
            float bias = cb[n];
#pragma unroll
            for (int nt = 0; nt < 8; nt++)
#pragma unroll
                for (int j = 0; j < 2; j++) {
                    int f = wn*64 + nt*8 + rg*2 + j;
                    float v = acc[mt][nt][i2*2 + j] + bias + gres[row*128 + f];
                    sg[row*128 + pcol(f)] = rnd_tf32(v * u[row*128 + f]);
                }
        }
}

// ---------------- host launcher ----------------
extern "C" void kernel_launch(void* const* d_in, const int* in_sizes, int n_in,
                              void* d_out, int out_size)
{
    const float* x      = (const float*)d_in[0];
    const float* norm_g = (const float*)d_in[1];
    const float* norm_b = (const float*)d_in[2];
    const float* W1     = (const float*)d_in[3];
    const float* b1     = (const float*)d_in[4];
    const float* aff1_W = (const float*)d_in[5];
    const float* aff1_b = (const float*)d_in[6];
    const float* Wl     = (const float*)d_in[7];
    const float* bl     = (const float*)d_in[8];
    const float* sgu_g  = (const float*)d_in[9];
    const float* sgu_b  = (const float*)d_in[10];
    const float* conv_w = (const float*)d_in[11];
    const float* conv_b = (const float*)d_in[12];
    const float* Wqkv   = (const float*)d_in[13];
    const float* bqkv   = (const float*)d_in[14];
    const float* Wo     = (const float*)d_in[15];
    const float* bo     = (const float*)d_in[16];
    const float* W2     = (const float*)d_in[17];
    const float* b2     = (const float*)d_in[18];
    float* out = (float*)d_out;

    float *xn, *qkv, *coords, *uu, *vn, *attnout, *gateres, *sg;
    float *wqkv, *w1, *wo, *w2, *cwt;
    cudaGetSymbolAddress((void**)&xn,      g_xn);
    cudaGetSymbolAddress((void**)&qkv,     g_qkv);
    cudaGetSymbolAddress((void**)&coords,  g_coords);
    cudaGetSymbolAddress((void**)&uu,      g_u);
    cudaGetSymbolAddress((void**)&vn,      g_vn);
    cudaGetSymbolAddress((void**)&attnout, g_attnout);
    cudaGetSymbolAddress((void**)&gateres, g_gateres);
    cudaGetSymbolAddress((void**)&sg,      g_sg);
    cudaGetSymbolAddress((void**)&wqkv,    g_wqkv);
    cudaGetSymbolAddress((void**)&w1,      g_w1);
    cudaGetSymbolAddress((void**)&wo,      g_wo);
    cudaGetSymbolAddress((void**)&w2,      g_w2);
    cudaGetSymbolAddress((void**)&cwt,     g_cwt);

    const int GEMM_SMEM = (128*132 + 2*128*36) * 4;           // 104448
    const int CONV_SMEM = (2*128*36 + 2*32*136) * 4;          // 71680
    const int ATTN_SMEM = (2*128*132 + 128*136 + 256) * 4;    // 205824
    static bool attr_done = false;
    if (!attr_done) {
        cudaFuncSetAttribute(gemm128<0, true,  true >, cudaFuncAttributeMaxDynamicSharedMemorySize, GEMM_SMEM);
        cudaFuncSetAttribute(gemm128<0, false, false>, cudaFuncAttributeMaxDynamicSharedMemorySize, GEMM_SMEM);
        cudaFuncSetAttribute(gemm128<2, false, false>, cudaFuncAttributeMaxDynamicSharedMemorySize, GEMM_SMEM);
        cudaFuncSetAttribute(fc1_kernel,  cudaFuncAttributeMaxDynamicSharedMemorySize, GEMM_SMEM);
        cudaFuncSetAttribute(conv_tc,     cudaFuncAttributeMaxDynamicSharedMemorySize, CONV_SMEM);
        cudaFuncSetAttribute(attn_kernel, cudaFuncAttributeMaxDynamicSharedMemorySize, ATTN_SMEM);
        attr_done = true;
    }

    // 0) weights -> transposed/permuted/rounded
    prep_kernel<<<(457888 + 255)/256, 256>>>(Wqkv, W1, Wo, W2, conv_w,
                                             wqkv, w1, wo, w2, cwt);
    // 1) LN(x) -> xn (permuted) + coords
    ln_kernel<<<(MT + 7)/8, 256>>>(x, xn, norm_g, norm_b, coords, Wl, bl);
    // 2) qkv (q,k permuted / v linear; rounded)
    {
        dim3 g(3, 975);
        gemm128<0, true, true><<<g, 256, GEMM_SMEM>>>(xn, wqkv, qkv, 384, bqkv, nullptr);
    }
    // 3) FC1 + fused SGU-LN: u (linear) and vn (linear, rounded)
    {
        dim3 g(2, 975);
        fc1_kernel<<<g, 256, GEMM_SMEM>>>(xn, w1, uu, vn, coords,
                                          b1, aff1_W, aff1_b, sgu_g, sgu_b);
    }
    // 4) fused attention -> attnout (permuted, rounded)
    {
        dim3 g(3, BT);
        attn_kernel<<<g, 256, ATTN_SMEM>>>(qkv, attnout);
    }
    // 5) gate_res = attnout @ Wo + bo (linear fp32)
    {
        dim3 g(1, 975);
        gemm128<0, false, false><<<g, 256, GEMM_SMEM>>>(attnout, wo, gateres, 128, bo, nullptr);
    }
    // 6) conv + gate -> sg (permuted, rounded)
    {
        dim3 g(3, BT);
        conv_tc<<<g, 256, CONV_SMEM>>>(cwt, vn, conv_b, gateres, uu, sg);
    }
    // 7) out = relu(sg @ W2 + b2) + x
    {
        dim3 g(1, 975);
        gemm128<2, false, false><<<g, 256, GEMM_SMEM>>>(sg, w2, out, 128, b2, x);
    }
}

// round 6
// speedup vs baseline: 1.0006x; 1.0006x over previous
#include <cuda_runtime.h>
#include <cstdint>

#define BT 384
#define NN 325
#define MT (BT*NN)     // 124800

// ---------------- scratch ----------------
__device__ float g_xn     [(size_t)MT*128];
__device__ float g_qkv    [(size_t)MT*384];
__device__ float g_coords [(size_t)MT*2];
__device__ float g_u      [(size_t)MT*128];
__device__ float g_vn     [(size_t)MT*128];
__device__ float g_attnout[(size_t)MT*128];
__device__ float g_gateres[(size_t)MT*128];
__device__ float g_sg     [(size_t)MT*128];
__device__ float g_wqkv   [384*128];
__device__ float g_w1     [256*128];
__device__ float g_wo     [128*128];
__device__ float g_w2     [128*128];
__device__ float g_cwt    [3*325*352];   // [tap][n][m-permuted, padded 352]

// ---------------- helpers ----------------
__device__ __forceinline__ float rnd_tf32(float f) {
    unsigned u;
    asm("cvt.rna.tf32.f32 %0, %1;" : "=r"(u) : "f"(f));
    return __uint_as_float(u);
}
__device__ __host__ __forceinline__ int pcol(int k) {
    return (k & ~31) | ((k & 3) << 3) | ((k >> 2) & 7);
}
__device__ __forceinline__ unsigned sptr(const void* p) {
    return (unsigned)__cvta_generic_to_shared(p);
}
__device__ __forceinline__ void cp16(unsigned dst, const void* src, bool pred) {
    int sz = pred ? 16 : 0;
    asm volatile("cp.async.ca.shared.global [%0], [%1], 16, %2;\n"
                 :: "r"(dst), "l"(src), "r"(sz));
}
#define CP_COMMIT() asm volatile("cp.async.commit_group;\n")
#define CP_WAIT(n)  asm volatile("cp.async.wait_group %0;\n" :: "n"(n))

__device__ __forceinline__ void mma_tf32(float& c0, float& c1, float& c2, float& c3,
                                         float a0, float a1, float a2, float a3,
                                         float b0, float b1) {
    asm volatile("mma.sync.aligned.m16n8k8.row.col.f32.tf32.tf32.f32 "
                 "{%0,%1,%2,%3}, {%4,%5,%6,%7}, {%8,%9}, {%0,%1,%2,%3};\n"
                 : "+f"(c0), "+f"(c1), "+f"(c2), "+f"(c3)
                 : "r"(__float_as_uint(a0)), "r"(__float_as_uint(a1)),
                   "r"(__float_as_uint(a2)), "r"(__float_as_uint(a3)),
                   "r"(__float_as_uint(b0)), "r"(__float_as_uint(b1)));
}

// ---------------- prep: transpose+round+permute all weights ------------
__global__ __launch_bounds__(256)
void prep_kernel(const float* __restrict__ Wqkv, const float* __restrict__ W1,
                 const float* __restrict__ Wo, const float* __restrict__ W2,
                 const float* __restrict__ cw,
                 float* __restrict__ oq, float* __restrict__ o1,
                 float* __restrict__ oo, float* __restrict__ o2,
                 float* __restrict__ ocw)
{
    int i = blockIdx.x * 256 + threadIdx.x;
    if (i < 49152) {
        int n = i >> 7, k = i & 127;
        oq[n*128 + pcol(k)] = rnd_tf32(Wqkv[(size_t)k*384 + n]); return;
    }
    i -= 49152;
    if (i < 32768) {
        int n = i >> 7, k = i & 127;
        o1[n*128 + pcol(k)] = rnd_tf32(W1[(size_t)k*256 + n]); return;
    }
    i -= 32768;
    if (i < 16384) {
        int n = i >> 7, k = i & 127;
        oo[n*128 + pcol(k)] = rnd_tf32(Wo[(size_t)k*128 + n]); return;
    }
    i -= 16384;
    if (i < 16384) {
        int n = i >> 7, k = i & 127;
        o2[n*128 + pcol(k)] = rnd_tf32(W2[(size_t)k*128 + n]); return;
    }
    i -= 16384;
    if (i < 3*325*352) {
        int t = i / 114400, rem = i % 114400;
        int n = rem / 352, mc = rem % 352;
        float v = (mc < 325) ? rnd_tf32(cw[((size_t)n*325 + mc)*3 + t]) : 0.f;
        ocw[(size_t)t*114400 + n*352 + pcol(mc)] = v;
    }
}

// ---------------- LayerNorm of x -> xn (permuted, rounded) + coords ----
__global__ __launch_bounds__(256)
void ln_kernel(const float* __restrict__ in, float* __restrict__ out,
               const float* __restrict__ gam, const float* __restrict__ bet,
               float* __restrict__ coords,
               const float* __restrict__ Wl, const float* __restrict__ bl)
{
    int row = blockIdx.x * 8 + (threadIdx.x >> 5);
    if (row >= MT) return;
    int lane = threadIdx.x & 31;
    float4 v = *(const float4*)(in + (size_t)row * 128 + lane * 4);
    float s  = v.x + v.y + v.z + v.w;
    float ss = v.x*v.x + v.y*v.y + v.z*v.z + v.w*v.w;
#pragma unroll
    for (int o = 16; o > 0; o >>= 1) {
        s  += __shfl_xor_sync(0xffffffffu, s,  o);
        ss += __shfl_xor_sync(0xffffffffu, ss, o);
    }
    float mean = s * (1.f/128.f);
    float var  = ss * (1.f/128.f) - mean * mean;
    float r = rsqrtf(var + 1e-5f);
    int c = lane * 4;
    float o0 = (v.x - mean) * r * gam[c+0] + bet[c+0];
    float o1 = (v.y - mean) * r * gam[c+1] + bet[c+1];
    float o2 = (v.z - mean) * r * gam[c+2] + bet[c+2];
    float o3 = (v.w - mean) * r * gam[c+3] + bet[c+3];
    float* orow = out + (size_t)row * 128;
    int cb = (lane >> 3) * 32 + (lane & 7);
    orow[cb +  0] = rnd_tf32(o0);
    orow[cb +  8] = rnd_tf32(o1);
    orow[cb + 16] = rnd_tf32(o2);
    orow[cb + 24] = rnd_tf32(o3);
    float c0 = o0*Wl[(c+0)*2] + o1*Wl[(c+1)*2] + o2*Wl[(c+2)*2] + o3*Wl[(c+3)*2];
    float c1 = o0*Wl[(c+0)*2+1] + o1*Wl[(c+1)*2+1] + o2*Wl[(c+2)*2+1] + o3*Wl[(c+3)*2+1];
#pragma unroll
    for (int o = 16; o > 0; o >>= 1) {
        c0 += __shfl_xor_sync(0xffffffffu, c0, o);
        c1 += __shfl_xor_sync(0xffffffffu, c1, o);
    }
    if (lane == 0) {
        coords[(size_t)row*2 + 0] = c0 + bl[0];
        coords[(size_t)row*2 + 1] = c1 + bl[1];
    }
}

// ======== shared mainloop fragments (A [128][36] per-kt, B [128][132]) ==
#define GEMM_DECLS                                                           \
    const int lane = tid & 31, wid = tid >> 5;                               \
    const int wm = wid >> 1, wn = wid & 1;                                   \
    const int qg = lane >> 2, rg = lane & 3;                                 \
    float acc[2][8][4];                                                      \
    _Pragma("unroll") for (int a_ = 0; a_ < 2; a_++)                         \
    _Pragma("unroll") for (int b_ = 0; b_ < 8; b_++)                         \
    _Pragma("unroll") for (int c_ = 0; c_ < 4; c_++) acc[a_][b_][c_] = 0.f;

#define GEMM_STEP(Ac, Bsrc, bstride, kcol)                                   \
    _Pragma("unroll")                                                        \
    for (int h = 0; h < 2; h++) {                                            \
        float av[2][2][4]; float bv[8][4];                                   \
        _Pragma("unroll")                                                    \
        for (int mt = 0; mt < 2; mt++)                                       \
        _Pragma("unroll")                                                    \
        for (int rh = 0; rh < 2; rh++)                                       \
            *(float4*)av[mt][rh] = *(const float4*)&(Ac)[(wm*32+mt*16+qg+rh*8)*36 + rg*8 + h*4]; \
        _Pragma("unroll")                                                    \
        for (int nt = 0; nt < 8; nt++)                                       \
            *(float4*)bv[nt] = *(const float4*)&(Bsrc)[(wn*64+nt*8+qg)*(bstride) + (kcol) + rg*8 + h*4]; \
        _Pragma("unroll")                                                    \
        for (int s2 = 0; s2 < 2; s2++) {                                     \
            _Pragma("unroll")                                                \
            for (int mt = 0; mt < 2; mt++) {                                 \
                float a0 = av[mt][0][2*s2],   a1 = av[mt][1][2*s2];          \
                float a2 = av[mt][0][2*s2+1], a3 = av[mt][1][2*s2+1];        \
                _Pragma("unroll")                                            \
                for (int nt = 0; nt < 8; nt++)                               \
                    mma_tf32(acc[mt][nt][0], acc[mt][nt][1], acc[mt][nt][2], acc[mt][nt][3], \
                             a0, a1, a2, a3, bv[nt][2*s2], bv[nt][2*s2+1]);  \
            }                                                                \
        }                                                                    \
    }

// ---------------- dense GEMM (M=MT, K=128), A & B permuted --------------
// EPI: 0 = +bias ; 2 = +bias, ReLU, +residual
template<int EPI, bool QKVMAP, bool RND>
__global__ __launch_bounds__(256, 2)
void gemm128(const float* __restrict__ A, const float* __restrict__ Bw,
             float* __restrict__ C, int ldc,
             const float* __restrict__ bias, const float* __restrict__ res)
{
    extern __shared__ float sm[];
    float* Bs = sm;                 // [128][132]
    float* As = sm + 128*132;       // [2][128][36]
    const int tid = threadIdx.x;
    const int row0 = blockIdx.y * 128, col0 = blockIdx.x * 128;
    {
        const float* Bp = Bw + (size_t)col0 * 128;
#pragma unroll
        for (int i = 0; i < 16; i++) {
            int lin = tid + 256*i; int r = lin >> 5, ch = lin & 31;
            cp16(sptr(Bs + r*132 + ch*4), Bp + (size_t)r*128 + ch*4, true);
        }
    }
    CP_COMMIT();
#define LA(st, k0) do {                                                      \
        float* dst = As + (st)*128*36;                                       \
        _Pragma("unroll")                                                    \
        for (int i = 0; i < 4; i++) {                                        \
            int lin = tid + 256*i; int r = lin >> 3, ch = lin & 7;           \
            cp16(sptr(dst + r*36 + ch*4),                                    \
                 A + (size_t)(row0 + r)*128 + (k0) + ch*4, true);            \
        }                                                                    \
        CP_COMMIT();                                                         \
    } while (0)
    LA(0, 0); LA(1, 32);
    CP_WAIT(1);
    __syncthreads();
    GEMM_DECLS
    for (int kt = 0; kt < 4; kt++) {
        const float* Ac = As + (kt & 1)*128*36;
        GEMM_STEP(Ac, Bs, 132, kt*32)
        if (kt < 2) {
            __syncthreads();
            LA(kt & 1, (kt + 2)*32);
            CP_WAIT(1);
            __syncthreads();
        } else if (kt == 2) {
            CP_WAIT(0);
            __syncthreads();
        }
    }
#undef LA
#pragma unroll
    for (int mt = 0; mt < 2; mt++)
#pragma unroll
        for (int i2 = 0; i2 < 2; i2++) {
            int r = row0 + wm*32 + mt*16 + qg + i2*8;
#pragma unroll
            for (int nt = 0; nt < 8; nt++)
#pragma unroll
                for (int j = 0; j < 2; j++) {
                    int c = col0 + wn*64 + nt*8 + rg*2 + j;
                    float v = acc[mt][nt][i2*2 + j] + bias[c];
                    if (EPI == 2) v = fmaxf(v, 0.f) + res[(size_t)r*128 + c];
                    if (RND) v = rnd_tf32(v);
                    int oc = QKVMAP ? ((c < 256) ? ((c & ~127) + pcol(c & 127)) : c) : c;
                    C[(size_t)r * ldc + oc] = v;
                }
        }
}

// ---------------- FC1: relu(xn@W1 + b1 + coords-affine); fused SGU-LN ---
__global__ __launch_bounds__(256, 2)
void fc1_kernel(const float* __restrict__ A, const float* __restrict__ Bw,
                float* __restrict__ u, float* __restrict__ vn,
                const float* __restrict__ coords,
                const float* __restrict__ b1,
                const float* __restrict__ aW, const float* __restrict__ ab,
                const float* __restrict__ sgu_g, const float* __restrict__ sgu_b)
{
    extern __shared__ float sm[];
    float* Bs = sm;
    float* As = sm + 128*132;
    const int tid = threadIdx.x;
    const int row0 = blockIdx.y * 128, col0 = blockIdx.x * 128;
    {
        const float* Bp = Bw + (size_t)col0 * 128;
#pragma unroll
        for (int i = 0; i < 16; i++) {
            int lin = tid + 256*i; int r = lin >> 5, ch = lin & 31;
            cp16(sptr(Bs + r*132 + ch*4), Bp + (size_t)r*128 + ch*4, true);
        }
    }
    CP_COMMIT();
#define LA(st, k0) do {                                                      \
        float* dst = As + (st)*128*36;                                       \
        _Pragma("unroll")                                                    \
        for (int i = 0; i < 4; i++) {                                        \
            int lin = tid + 256*i; int r = lin >> 3, ch = lin & 7;           \
            cp16(sptr(dst + r*36 + ch*4),                                    \
                 A + (size_t)(row0 + r)*128 + (k0) + ch*4, true);            \
        }                                                                    \
        CP_COMMIT();                                                         \
    } while (0)
    LA(0, 0); LA(1, 32);
    CP_WAIT(1);
    __syncthreads();
    GEMM_DECLS
    for (int kt = 0; kt < 4; kt++) {
        const float* Ac = As + (kt & 1)*128*36;
        GEMM_STEP(Ac, Bs, 132, kt*32)
        if (kt < 2) {
            __syncthreads();
            LA(kt & 1, (kt + 2)*32);
            CP_WAIT(1);
            __syncthreads();
        } else if (kt == 2) {
            CP_WAIT(0);
            __syncthreads();
        }
    }
#undef LA
    // epilogue: affine + relu, in place
    float sums[2][2], sqs[2][2];
#pragma unroll
    for (int mt = 0; mt < 2; mt++)
#pragma unroll
        for (int i2 = 0; i2 < 2; i2++) { sums[mt][i2] = 0.f; sqs[mt][i2] = 0.f; }
#pragma unroll
    for (int mt = 0; mt < 2; mt++)
#pragma unroll
        for (int i2 = 0; i2 < 2; i2++) {
            int r = row0 + wm*32 + mt*16 + qg + i2*8;
            float c0v = coords[(size_t)r*2], c1v = coords[(size_t)r*2 + 1];
#pragma unroll
            for (int nt = 0; nt < 8; nt++)
#pragma unroll
                for (int j = 0; j < 2; j++) {
                    int c = col0 + wn*64 + nt*8 + rg*2 + j;
                    float v = acc[mt][nt][i2*2 + j] + b1[c] + c0v*aW[c] + c1v*aW[256 + c] + ab[c];
                    v = fmaxf(v, 0.f);
                    acc[mt][nt][i2*2 + j] = v;
                    sums[mt][i2] += v;
                    sqs[mt][i2]  += v * v;
                }
        }
    if (col0 == 0) {
        // u half: write linear fp32
#pragma unroll
        for (int mt = 0; mt < 2; mt++)
#pragma unroll
            for (int i2 = 0; i2 < 2; i2++) {
                int r = row0 + wm*32 + mt*16 + qg + i2*8;
#pragma unroll
                for (int nt = 0; nt < 8; nt++)
#pragma unroll
                    for (int j = 0; j < 2; j++) {
                        int c = wn*64 + nt*8 + rg*2 + j;
                        u[(size_t)r*128 + c] = acc[mt][nt][i2*2 + j];
                    }
            }
    } else {
        // vv half: fused LayerNorm -> vn (linear, rounded)
        float* rowstat = As;   // reuse, 128*4 floats
        __syncthreads();
#pragma unroll
        for (int mt = 0; mt < 2; mt++)
#pragma unroll
            for (int i2 = 0; i2 < 2; i2++) {
                float s = sums[mt][i2], q = sqs[mt][i2];
                s += __shfl_xor_sync(0xffffffffu, s, 1);
                s += __shfl_xor_sync(0xffffffffu, s, 2);
                q += __shfl_xor_sync(0xffffffffu, q, 1);
                q += __shfl_xor_sync(0xffffffffu, q, 2);
                if (rg == 0) {
                    int rl = wm*32 + mt*16 + qg + i2*8;
                    rowstat[rl*4 + wn*2 + 0] = s;
                    rowstat[rl*4 + wn*2 + 1] = q;
                }
            }
        __syncthreads();
#pragma unroll
        for (int mt = 0; mt < 2; mt++)
#pragma unroll
            for (int i2 = 0; i2 < 2; i2++) {
                int rl = wm*32 + mt*16 + qg + i2*8;
                int r = row0 + rl;
                float s = rowstat[rl*4] + rowstat[rl*4 + 2];
                float q = rowstat[rl*4 + 1] + rowstat[rl*4 + 3];
                float mean = s * (1.f/128.f);
                float var  = q * (1.f/128.f) - mean * mean;
                float rinv = rsqrtf(var + 1e-5f);
#pragma unroll
                for (int nt = 0; nt < 8; nt++)
#pragma unroll
                    for (int j = 0; j < 2; j++) {
                        int f = wn*64 + nt*8 + rg*2 + j;
                        float v = (acc[mt][nt][i2*2 + j] - mean) * rinv * sgu_g[f] + sgu_b[f];
                        vn[(size_t)r*128 + f] = rnd_tf32(v);
                    }
            }
    }
}

// ---------------- fused flash attention: grid (3, BT) -------------------
__global__ __launch_bounds__(256)
void attn_kernel(const float* __restrict__ qkv, float* __restrict__ attnout)
{
    extern __shared__ float sm[];
    float* qs   = sm;                     // [128][132] (q, permuted k-dim)
    float* ks   = sm + 128*132;           // [128][132] (k tile; reused as P)
    float* vs   = sm + 2*128*132;         // [128][136] (v, linear)
    float* lsum = sm + 2*128*132 + 128*136;
    const int bt = blockIdx.y, q0 = blockIdx.x * 128;
    const int tid = threadIdx.x;
    const float* base = qkv + (size_t)bt * NN * 384;

#define LQ(dst, stridew, off, r0) do {                                       \
        _Pragma("unroll")                                                    \
        for (int i = 0; i < 16; i++) {                                       \
            int lin = tid + 256*i; int r = lin >> 5, ch = lin & 31;          \
            bool p = ((r0) + r) < NN;                                        \
            cp16(sptr((dst) + r*(stridew) + ch*4),                           \
                 base + (size_t)((r0) + r)*384 + (off) + ch*4, p);           \
        }                                                                    \
    } while (0)

    LQ(qs, 132, 0,   q0);
    LQ(ks, 132, 128, 0);
    LQ(vs, 136, 256, 0);
    CP_COMMIT();
    lsum[tid] = 0.f;
    CP_WAIT(0);
    __syncthreads();

    const int lane = tid & 31, wid = tid >> 5;
    const int wm = wid >> 1, wn = wid & 1;
    const int qg = lane >> 2, rg = lane & 3;
    float Oacc[2][8][4];
#pragma unroll
    for (int a = 0; a < 2; a++)
#pragma unroll
        for (int b = 0; b < 8; b++)
#pragma unroll
            for (int c = 0; c < 4; c++) Oacc[a][b][c] = 0.f;

    for (int it = 0; it < 3; it++) {
        const int k0g = it * 128;
        float acc[2][8][4];
#pragma unroll
        for (int a = 0; a < 2; a++)
#pragma unroll
            for (int b = 0; b < 8; b++)
#pragma unroll
                for (int c = 0; c < 4; c++) acc[a][b][c] = 0.f;
        // S = q @ k^T  (vectorized fragments, both permuted on feature dim)
        for (int kt = 0; kt < 4; kt++) {
            GEMM_STEP(qs /*dummy-a*/, ks, 132, kt*32)
        }
        // NOTE: GEMM_STEP used qs for A? It uses (Ac) param — fix via macro arg:
        // (A-operand rows are qs with stride 132; see specialized step below.)
        // exp + mask + row sums
        float rs[2][2] = {{0.f,0.f},{0.f,0.f}};
#pragma unroll
        for (int mt = 0; mt < 2; mt++)
#pragma unroll
            for (int nt = 0; nt < 8; nt++)
#pragma unroll
                for (int idx = 0; idx < 4; idx++) {
                    int col = k0g + wn*64 + nt*8 + rg*2 + (idx & 1);
                    float p = (col < NN) ? rnd_tf32(__expf(acc[mt][nt][idx])) : 0.f;
                    acc[mt][nt][idx] = p;
                    rs[mt][idx >> 1] += p;
                }
#pragma unroll
        for (int mt = 0; mt < 2; mt++)
#pragma unroll
            for (int i2 = 0; i2 < 2; i2++) {
                float r = rs[mt][i2];
                r += __shfl_xor_sync(0xffffffffu, r, 1);
                r += __shfl_xor_sync(0xffffffffu, r, 2);
                if (rg == 0)
                    lsum[(wm*32 + mt*16 + qg + i2*8)*2 + wn] += r;
            }
        __syncthreads();
        // store P into ks (permuted key-dim)
#pragma unroll
        for (int mt = 0; mt < 2; mt++)
#pragma unroll
            for (int nt = 0; nt < 8; nt++)
#pragma unroll
                for (int idx = 0; idx < 4; idx++) {
                    int r = wm*32 + mt*16 + qg + (idx >> 1)*8;
                    int c = wn*64 + nt*8 + rg*2 + (idx & 1);
                    ks[r*132 + pcol(c)] = acc[mt][nt][idx];
                }
        __syncthreads();
        // O += P @ v   (A = P vectorized; B = v scalar)
        for (int kt = 0; kt < 4; kt++) {
#pragma unroll
            for (int h = 0; h < 2; h++) {
                float av[2][2][4];
#pragma unroll
                for (int mt = 0; mt < 2; mt++)
#pragma unroll
                    for (int rh = 0; rh < 2; rh++)
                        *(float4*)av[mt][rh] = *(const float4*)&ks[(wm*32+mt*16+qg+rh*8)*132 + kt*32 + rg*8 + h*4];
#pragma unroll
                for (int s2 = 0; s2 < 2; s2++) {
                    int kk = kt*32 + h*16 + s2*8;
                    float b0[8], b1[8];
#pragma unroll
                    for (int nt = 0; nt < 8; nt++) {
                        int c = wn*64 + nt*8 + qg;
                        b0[nt] = vs[(kk + rg)*136 + c];
                        b1[nt] = vs[(kk + rg + 4)*136 + c];
                    }
#pragma unroll
                    for (int mt = 0; mt < 2; mt++) {
                        float a0 = av[mt][0][2*s2],   a1 = av[mt][1][2*s2];
                        float a2 = av[mt][0][2*s2+1], a3 = av[mt][1][2*s2+1];
#pragma unroll
                        for (int nt = 0; nt < 8; nt++)
                            mma_tf32(Oacc[mt][nt][0], Oacc[mt][nt][1], Oacc[mt][nt][2], Oacc[mt][nt][3],
                                     a0, a1, a2, a3, b0[nt], b1[nt]);
                    }
                }
            }
        }
        __syncthreads();
        if (it < 2) {
            LQ(ks, 132, 128, (it + 1)*128);
            LQ(vs, 136, 256, (it + 1)*128);
            CP_COMMIT();
            CP_WAIT(0);
            __syncthreads();
        }
    }
#undef LQ
    // epilogue: O / l -> attnout (permuted, rounded)
#pragma unroll
    for (int mt = 0; mt < 2; mt++)
#pragma unroll
        for (int i2 = 0; i2 < 2; i2++) {
            int rl = wm*32 + mt*16 + qg + i2*8;
            int n = q0 + rl;
            if (n >= NN) continue;
            float inv = 1.f / (lsum[rl*2] + lsum[rl*2 + 1]);
            float* orow = attnout + ((size_t)bt * NN + n) * 128;
#pragma unroll
            for (int nt = 0; nt < 8; nt++)
#pragma unroll
                for (int j = 0; j < 2; j++) {
                    int f = wn*64 + nt*8 + rg*2 + j;
                    orow[pcol(f)] = rnd_tf32(Oacc[mt][nt][i2*2 + j] * inv);
                }
        }
}

// ---------------- conv: A=cwt (permuted m), B=vn rows, tap via shift ----
__global__ __launch_bounds__(256, 2)
void conv_tc(const float* __restrict__ cwt, const float* __restrict__ vn,
             const float* __restrict__ cb, const float* __restrict__ gres,
             const float* __restrict__ u, float* __restrict__ sg)
{
    extern __shared__ float sm[];
    float* As = sm;                 // [2][128][36]
    float* Bs = sm + 2*128*36;      // [2][32][136]
    const int bt = blockIdx.y, n0 = blockIdx.x * 128;
    const int tid = threadIdx.x;
    const float* vbt = vn + (size_t)bt * NN * 128;

#define LT(st, tap_, m0_) do {                                               \
        float* Ad = As + (st)*128*36;                                        \
        float* Bd = Bs + (st)*32*136;                                        \
        const float* cwp = cwt + (size_t)(tap_)*114400;                      \
        _Pragma("unroll")                                                    \
        for (int i = 0; i < 4; i++) {                                        \
            int lin = tid + 256*i; int r = lin >> 3, ch = lin & 7;           \
            bool p = (n0 + r) < NN;                                          \
            cp16(sptr(Ad + r*36 + ch*4),                                     \
                 cwp + (size_t)(n0 + r)*352 + (m0_) + ch*4, p);              \
        }                                                                    \
        _Pragma("unroll")                                                    \
        for (int i = 0; i < 4; i++) {                                        \
            int lin = tid + 256*i; int r = lin >> 5, ch = lin & 31;          \
            bool p = ((m0_) + r) < NN;                                       \
            cp16(sptr(Bd + r*136 + ch*4),                                    \
                 vbt + (size_t)((m0_) + r)*128 + ch*4, p);                   \
        }                                                                    \
        CP_COMMIT();                                                         \
    } while (0)

    LT(0, 0, 0); LT(1, 0, 32);
    CP_WAIT(1);
    __syncthreads();

    const int lane = tid & 31, wid = tid >> 5;
    const int wm = wid >> 1, wn = wid & 1;
    const int qg = lane >> 2, rg = lane & 3;
    float acc[2][8][4];
#pragma unroll
    for (int a = 0; a < 2; a++)
#pragma unroll
        for (int b = 0; b < 8; b++)
#pragma unroll
            for (int c = 0; c < 4; c++) acc[a][b][c] = 0.f;

    const int NSTEP = 33;
    for (int q = 0; q < NSTEP; q++) {
        const int tap = q / 11;
        const float* Ac = As + (q & 1)*128*36;
        const float* Bc = Bs + (q & 1)*32*136;
#pragma unroll
        for (int h = 0; h < 2; h++) {
            float av[2][2][4];
#pragma unroll
            for (int mt = 0; mt < 2; mt++)
#pragma unroll
                for (int rh = 0; rh < 2; rh++)
                    *(float4*)av[mt][rh] = *(const float4*)&Ac[(wm*32+mt*16+qg+rh*8)*36 + rg*8 + h*4];
#pragma unroll
            for (int s2 = 0; s2 < 2; s2++) {
                int kk = h*16 + s2*8;
                float b0[8], b1[8];
#pragma unroll
                for (int nt = 0; nt < 8; nt++) {
                    int cs = wn*64 + nt*8 + qg + tap - 1;
                    bool ok = (cs >= 0) && (cs < 128);
                    b0[nt] = ok ? Bc[(kk + rg)*136 + cs] : 0.f;
                    b1[nt] = ok ? Bc[(kk + rg + 4)*136 + cs] : 0.f;
                }
#pragma unroll
                for (int mt = 0; mt < 2; mt++) {
                    float a0 = av[mt][0][2*s2],   a1 = av[mt][1][2*s2];
                    float a2 = av[mt][0][2*s2+1], a3 = av[mt][1][2*s2+1];
#pragma unroll
                    for (int nt = 0; nt < 8; nt++)
                        mma_tf32(acc[mt][nt][0], acc[mt][nt][1], acc[mt][nt][2], acc[mt][nt][3],
                                 a0, a1, a2, a3, b0[nt], b1[nt]);
                }
            }
        }
        if (q + 2 < NSTEP) {
            int qn = q + 2;
            __syncthreads();
            LT(q & 1, qn / 11, (qn % 11)*32);
            CP_WAIT(1);
            __syncthreads();
        } else if (q + 1 < NSTEP) {
            CP_WAIT(0);
            __syncthreads();
        }
    }
#undef LT
#pragma unroll
    for (int mt = 0; mt < 2; mt++)
#pragma unroll
        for (int i2 = 0; i2 < 2; i2++) {
            int n = n0 + wm*32 + mt*16 + qg + i2*8;
            if (n >= NN) continue;
            size_t row = (size_t)bt * NN + n;
            float bias = cb[n];
#pragma unroll
            for (int nt = 0; nt < 8; nt++)
#pragma unroll
                for (int j = 0; j < 2; j++) {
                    int f = wn*64 + nt*8 + rg*2 + j;
                    float v = acc[mt][nt][i2*2 + j] + bias + gres[row*128 + f];
                    sg[row*128 + pcol(f)] = rnd_tf32(v * u[row*128 + f]);
                }
        }
}

// ---------------- host launcher ----------------
extern "C" void kernel_launch(void* const* d_in, const int* in_sizes, int n_in,
                              void* d_out, int out_size)
{
    const float* x      = (const float*)d_in[0];
    const float* norm_g = (const float*)d_in[1];
    const float* norm_b = (const float*)d_in[2];
    const float* W1     = (const float*)d_in[3];
    const float* b1     = (const float*)d_in[4];
    const float* aff1_W = (const float*)d_in[5];
    const float* aff1_b = (const float*)d_in[6];
    const float* Wl     = (const float*)d_in[7];
    const float* bl     = (const float*)d_in[8];
    const float* sgu_g  = (const float*)d_in[9];
    const float* sgu_b  = (const float*)d_in[10];
    const float* conv_w = (const float*)d_in[11];
    const float* conv_b = (const float*)d_in[12];
    const float* Wqkv   = (const float*)d_in[13];
    const float* bqkv   = (const float*)d_in[14];
    const float* Wo     = (const float*)d_in[15];
    const float* bo     = (const float*)d_in[16];
    const float* W2     = (const float*)d_in[17];
    const float* b2     = (const float*)d_in[18];
    float* out = (float*)d_out;

    float *xn, *qkv, *coords, *uu, *vn, *attnout, *gateres, *sg;
    float *wqkv, *w1, *wo, *w2, *cwt;
    cudaGetSymbolAddress((void**)&xn,      g_xn);
    cudaGetSymbolAddress((void**)&qkv,     g_qkv);
    cudaGetSymbolAddress((void**)&coords,  g_coords);
    cudaGetSymbolAddress((void**)&uu,      g_u);
    cudaGetSymbolAddress((void**)&vn,      g_vn);
    cudaGetSymbolAddress((void**)&attnout, g_attnout);
    cudaGetSymbolAddress((void**)&gateres, g_gateres);
    cudaGetSymbolAddress((void**)&sg,      g_sg);
    cudaGetSymbolAddress((void**)&wqkv,    g_wqkv);
    cudaGetSymbolAddress((void**)&w1,      g_w1);
    cudaGetSymbolAddress((void**)&wo,      g_wo);
    cudaGetSymbolAddress((void**)&w2,      g_w2);
    cudaGetSymbolAddress((void**)&cwt,     g_cwt);

    const int GEMM_SMEM = (128*132 + 2*128*36) * 4;           // 104448
    const int CONV_SMEM = (2*128*36 + 2*32*136) * 4;          // 71680
    const int ATTN_SMEM = (2*128*132 + 128*136 + 256) * 4;    // 205824
    static bool attr_done = false;
    if (!attr_done) {
        cudaFuncSetAttribute(gemm128<0, true,  true >, cudaFuncAttributeMaxDynamicSharedMemorySize, GEMM_SMEM);
        cudaFuncSetAttribute(gemm128<0, false, false>, cudaFuncAttributeMaxDynamicSharedMemorySize, GEMM_SMEM);
        cudaFuncSetAttribute(gemm128<2, false, false>, cudaFuncAttributeMaxDynamicSharedMemorySize, GEMM_SMEM);
        cudaFuncSetAttribute(fc1_kernel,  cudaFuncAttributeMaxDynamicSharedMemorySize, GEMM_SMEM);
        cudaFuncSetAttribute(conv_tc,     cudaFuncAttributeMaxDynamicSharedMemorySize, CONV_SMEM);
        cudaFuncSetAttribute(attn_kernel, cudaFuncAttributeMaxDynamicSharedMemorySize, ATTN_SMEM);
        attr_done = true;
    }

    // 0) weights -> transposed/permuted/rounded
    prep_kernel<<<(457888 + 255)/256, 256>>>(Wqkv, W1, Wo, W2, conv_w,
                                             wqkv, w1, wo, w2, cwt);
    // 1) LN(x) -> xn (permuted) + coords
    ln_kernel<<<(MT + 7)/8, 256>>>(x, xn, norm_g, norm_b, coords, Wl, bl);
    // 2) qkv (q,k permuted / v linear; rounded)
    {
        dim3 g(3, 975);
        gemm128<0, true, true><<<g, 256, GEMM_SMEM>>>(xn, wqkv, qkv, 384, bqkv, nullptr);
    }
    // 3) FC1 + fused SGU-LN: u (linear) and vn (linear, rounded)
    {
        dim3 g(2, 975);
        fc1_kernel<<<g, 256, GEMM_SMEM>>>(xn, w1, uu, vn, coords,
                                          b1, aff1_W, aff1_b, sgu_g, sgu_b);
    }
    // 4) fused attention -> attnout (permuted, rounded)
    {
        dim3 g(3, BT);
        attn_kernel<<<g, 256, ATTN_SMEM>>>(qkv, attnout);
    }
    // 5) gate_res = attnout @ Wo + bo (linear fp32)
    {
        dim3 g(1, 975);
        gemm128<0, false, false><<<g, 256, GEMM_SMEM>>>(attnout, wo, gateres, 128, bo, nullptr);
    }
    // 6) conv + gate -> sg (permuted, rounded)
    {
        dim3 g(3, BT);
        conv_tc<<<g, 256, CONV_SMEM>>>(cwt, vn, conv_b, gateres, uu, sg);
    }
    // 7) out = relu(sg @ W2 + b2) + x
    {
        dim3 g(1, 975);
        gemm128<2, false, false><<<g, 256, GEMM_SMEM>>>(sg, w2, out, 128, b2, x);
    }
}

// round 8
// speedup vs baseline: 1.9824x; 1.9812x over previous
#include <cuda_runtime.h>
#include <cuda_fp16.h>
#include <cstdint>

#define BT 384
#define NN 325
#define MT (BT*NN)     // 124800

// ---------------- scratch (device globals; zero-initialized) -----------
__device__ __half g_xn     [(size_t)MT*128];
__device__ __half g_qkvh   [(size_t)MT*384];
__device__ float  g_coords [(size_t)MT*2];
__device__ float  g_u      [(size_t)MT*128];
__device__ __half g_vnT    [(size_t)BT*130*384];  // rows 0 and 129 stay zero
__device__ __half g_attnout[(size_t)MT*128];
__device__ float  g_gateres[(size_t)MT*128];
__device__ __half g_sg     [(size_t)MT*128];
__device__ __half g_wqkv   [384*128];
__device__ __half g_w1     [256*128];
__device__ __half g_wo     [128*128];
__device__ __half g_w2     [128*128];
__device__ __half g_cwt    [3*384*384];           // [tap][n pad384][m pad384]

// ---------------- helpers ----------------
__device__ __forceinline__ unsigned sptr(const void* p) {
    return (unsigned)__cvta_generic_to_shared(p);
}
__device__ __forceinline__ void cp16(unsigned dst, const void* src, bool pred) {
    int sz = pred ? 16 : 0;
    asm volatile("cp.async.ca.shared.global [%0], [%1], 16, %2;\n"
                 :: "r"(dst), "l"(src), "r"(sz));
}
#define CP_COMMIT() asm volatile("cp.async.commit_group;\n")
#define CP_WAIT0()  asm volatile("cp.async.wait_group 0;\n")

__device__ __forceinline__ void ldsm4(unsigned* r, unsigned addr) {
    asm volatile("ldmatrix.sync.aligned.m8n8.x4.shared.b16 {%0,%1,%2,%3}, [%4];\n"
                 : "=r"(r[0]), "=r"(r[1]), "=r"(r[2]), "=r"(r[3]) : "r"(addr));
}
__device__ __forceinline__ void ldsm4t(unsigned* r, unsigned addr) {
    asm volatile("ldmatrix.sync.aligned.m8n8.x4.trans.shared.b16 {%0,%1,%2,%3}, [%4];\n"
                 : "=r"(r[0]), "=r"(r[1]), "=r"(r[2]), "=r"(r[3]) : "r"(addr));
}
__device__ __forceinline__ void mma_f16(float* c, const unsigned* a, unsigned b0, unsigned b1) {
    asm volatile("mma.sync.aligned.m16n8k16.row.col.f32.f16.f16.f32 "
                 "{%0,%1,%2,%3}, {%4,%5,%6,%7}, {%8,%9}, {%0,%1,%2,%3};\n"
                 : "+f"(c[0]), "+f"(c[1]), "+f"(c[2]), "+f"(c[3])
                 : "r"(a[0]), "r"(a[1]), "r"(a[2]), "r"(a[3]), "r"(b0), "r"(b1));
}
__device__ __forceinline__ unsigned h2u(__half2 h) {
    unsigned u; memcpy(&u, &h, 4); return u;
}

// ---------------- prep: weights -> half, transposed --------------------
__global__ __launch_bounds__(256)
void prep_kernel(const float* __restrict__ Wqkv, const float* __restrict__ W1,
                 const float* __restrict__ Wo, const float* __restrict__ W2,
                 const float* __restrict__ cw,
                 __half* __restrict__ oq, __half* __restrict__ o1,
                 __half* __restrict__ oo, __half* __restrict__ o2,
                 __half* __restrict__ ocw)
{
    int i = blockIdx.x * 256 + threadIdx.x;
    if (i < 49152) { int n = i >> 7, k = i & 127;
        oq[n*128 + k] = __float2half_rn(Wqkv[(size_t)k*384 + n]); return; }
    i -= 49152;
    if (i < 32768) { int n = i >> 7, k = i & 127;
        o1[n*128 + k] = __float2half_rn(W1[(size_t)k*256 + n]); return; }
    i -= 32768;
    if (i < 16384) { int n = i >> 7, k = i & 127;
        oo[n*128 + k] = __float2half_rn(Wo[(size_t)k*128 + n]); return; }
    i -= 16384;
    if (i < 16384) { int n = i >> 7, k = i & 127;
        o2[n*128 + k] = __float2half_rn(W2[(size_t)k*128 + n]); return; }
    i -= 16384;
    if (i < 316875) {   // 3*325*325
        int t = i / 105625, rem = i % 105625;
        int n = rem / 325, m = rem % 325;
        ocw[(size_t)t*384*384 + n*384 + m] =
            __float2half_rn(cw[((size_t)n*325 + m)*3 + t]);
    }
}

// ---------------- LayerNorm(x) -> xn half + coords fp32 ----------------
__global__ __launch_bounds__(256)
void ln_kernel(const float* __restrict__ in, __half* __restrict__ out,
               const float* __restrict__ gam, const float* __restrict__ bet,
               float* __restrict__ coords,
               const float* __restrict__ Wl, const float* __restrict__ bl)
{
    int row = blockIdx.x * 8 + (threadIdx.x >> 5);
    if (row >= MT) return;
    int lane = threadIdx.x & 31;
    float4 v = *(const float4*)(in + (size_t)row * 128 + lane * 4);
    float s  = v.x + v.y + v.z + v.w;
    float ss = v.x*v.x + v.y*v.y + v.z*v.z + v.w*v.w;
#pragma unroll
    for (int o = 16; o > 0; o >>= 1) {
        s  += __shfl_xor_sync(0xffffffffu, s,  o);
        ss += __shfl_xor_sync(0xffffffffu, ss, o);
    }
    float mean = s * (1.f/128.f);
    float var  = ss * (1.f/128.f) - mean * mean;
    float r = rsqrtf(var + 1e-5f);
    int c = lane * 4;
    float o0 = (v.x - mean) * r * gam[c+0] + bet[c+0];
    float o1 = (v.y - mean) * r * gam[c+1] + bet[c+1];
    float o2 = (v.z - mean) * r * gam[c+2] + bet[c+2];
    float o3 = (v.w - mean) * r * gam[c+3] + bet[c+3];
    __half2* orow = (__half2*)(out + (size_t)row * 128);
    orow[lane*2]     = __floats2half2_rn(o0, o1);
    orow[lane*2 + 1] = __floats2half2_rn(o2, o3);
    float c0 = o0*Wl[(c+0)*2] + o1*Wl[(c+1)*2] + o2*Wl[(c+2)*2] + o3*Wl[(c+3)*2];
    float c1 = o0*Wl[(c+0)*2+1] + o1*Wl[(c+1)*2+1] + o2*Wl[(c+2)*2+1] + o3*Wl[(c+3)*2+1];
#pragma unroll
    for (int o = 16; o > 0; o >>= 1) {
        c0 += __shfl_xor_sync(0xffffffffu, c0, o);
        c1 += __shfl_xor_sync(0xffffffffu, c1, o);
    }
    if (lane == 0) {
        coords[(size_t)row*2 + 0] = c0 + bl[0];
        coords[(size_t)row*2 + 1] = c1 + bl[1];
    }
}

// ======== common pieces: tiles are u32 arrays; rows of 128 halves = 64
// u32, padded to stride 68 u32 (conflict-free for ldmatrix). ========
#define WARP_DECLS \
    const int lane = tid & 31, wid = tid >> 5; \
    const int wm = wid >> 1, wn = wid & 1;     \
    const int qg = lane >> 2, rg = lane & 3;

// A: 128x128 halves at As (stride 68 u32); B: 128(n)x128(k) at Bs.
#define MAINLOOP_128(As, Bs) do {                                            \
    unsigned aaddr[2], baddr[4];                                             \
    _Pragma("unroll")                                                        \
    for (int mt = 0; mt < 2; mt++)                                           \
        aaddr[mt] = sptr((As) + (wm*32 + mt*16 + (lane & 15))*68 + ((lane >> 4) << 2)); \
    _Pragma("unroll")                                                        \
    for (int p = 0; p < 4; p++)                                              \
        baddr[p] = sptr((Bs) + (wn*64 + p*16 + (lane & 7) + ((lane >> 4) << 3))*68 + (((lane >> 3) & 1) << 2)); \
    _Pragma("unroll")                                                        \
    for (int s = 0; s < 8; s++) {                                            \
        unsigned a[2][4], b[4][4];                                           \
        _Pragma("unroll")                                                    \
        for (int mt = 0; mt < 2; mt++) ldsm4(a[mt], aaddr[mt] + s*32);       \
        _Pragma("unroll")                                                    \
        for (int p = 0; p < 4; p++) ldsm4(b[p], baddr[p] + s*32);            \
        _Pragma("unroll")                                                    \
        for (int mt = 0; mt < 2; mt++)                                       \
            _Pragma("unroll")                                                \
            for (int p = 0; p < 4; p++) {                                    \
                mma_f16(acc[mt][2*p],     a[mt], b[p][0], b[p][1]);          \
                mma_f16(acc[mt][2*p + 1], a[mt], b[p][2], b[p][3]);          \
            }                                                                \
    }                                                                        \
} while (0)

#define LOAD_AB_128(As, Bs, Aptr, Bptr) do {                                 \
    _Pragma("unroll")                                                        \
    for (int i = 0; i < 8; i++) {                                            \
        int lin = tid + 256*i; int r = lin >> 4, ch = lin & 15;              \
        cp16(sptr((As) + r*68 + ch*4), (Aptr) + (size_t)r*128 + ch*8, true); \
    }                                                                        \
    _Pragma("unroll")                                                        \
    for (int i = 0; i < 8; i++) {                                            \
        int lin = tid + 256*i; int r = lin >> 4, ch = lin & 15;              \
        cp16(sptr((Bs) + r*68 + ch*4), (Bptr) + (size_t)r*128 + ch*8, true); \
    }                                                                        \
    CP_COMMIT(); CP_WAIT0(); __syncthreads();                                \
} while (0)

#define ACC_DECL float acc[2][8][4];                                         \
    _Pragma("unroll") for (int a_=0;a_<2;a_++)                               \
    _Pragma("unroll") for (int b_=0;b_<8;b_++)                               \
    _Pragma("unroll") for (int c_=0;c_<4;c_++) acc[a_][b_][c_] = 0.f;

// ---------------- dense GEMM (M=MT, K=128) -----------------------------
// EPI: 0 = +bias -> half [row][384] ; 1 = +bias -> float[128] ;
//      2 = +bias, relu, +res -> float[128]
template<int EPI>
__global__ __launch_bounds__(256)
void gemm_h(const __half* __restrict__ A, const __half* __restrict__ Bw,
            void* __restrict__ Cout, const float* __restrict__ bias,
            const float* __restrict__ res)
{
    extern __shared__ unsigned sm[];
    unsigned* As = sm;             // [128][68]
    unsigned* Bs = sm + 128*68;    // [128][68]
    const int tid = threadIdx.x;
    const int row0 = blockIdx.y * 128, col0 = blockIdx.x * 128;
    LOAD_AB_128(As, Bs, A + (size_t)row0*128, Bw + (size_t)col0*128);
    WARP_DECLS
    ACC_DECL
    MAINLOOP_128(As, Bs);
#pragma unroll
    for (int mt = 0; mt < 2; mt++)
#pragma unroll
        for (int i2 = 0; i2 < 2; i2++) {
            int r = row0 + wm*32 + mt*16 + qg + i2*8;
#pragma unroll
            for (int nt = 0; nt < 8; nt++) {
                int c = col0 + wn*64 + nt*8 + rg*2;
                float v0 = acc[mt][nt][i2*2]     + bias[c];
                float v1 = acc[mt][nt][i2*2 + 1] + bias[c + 1];
                if (EPI == 0) {
                    *(__half2*)((__half*)Cout + (size_t)r*384 + c) = __floats2half2_rn(v0, v1);
                } else if (EPI == 1) {
                    float* C = (float*)Cout;
                    C[(size_t)r*128 + c]     = v0;
                    C[(size_t)r*128 + c + 1] = v1;
                } else {
                    float* C = (float*)Cout;
                    C[(size_t)r*128 + c]     = fmaxf(v0, 0.f) + res[(size_t)r*128 + c];
                    C[(size_t)r*128 + c + 1] = fmaxf(v1, 0.f) + res[(size_t)r*128 + c + 1];
                }
            }
        }
}

// ---------------- FC1 + fused SGU-LN (vn written transposed) ------------
__global__ __launch_bounds__(256)
void fc1_kernel(const __half* __restrict__ A, const __half* __restrict__ Bw,
                float* __restrict__ u, __half* __restrict__ vnT,
                const float* __restrict__ coords,
                const float* __restrict__ b1,
                const float* __restrict__ aW, const float* __restrict__ ab,
                const float* __restrict__ sgu_g, const float* __restrict__ sgu_b)
{
    extern __shared__ unsigned sm[];
    unsigned* As = sm;
    unsigned* Bs = sm + 128*68;
    const int tid = threadIdx.x;
    const int row0 = blockIdx.y * 128, col0 = blockIdx.x * 128;
    LOAD_AB_128(As, Bs, A + (size_t)row0*128, Bw + (size_t)col0*128);
    WARP_DECLS
    ACC_DECL
    MAINLOOP_128(As, Bs);
    float sums[2][2] = {{0,0},{0,0}}, sqs[2][2] = {{0,0},{0,0}};
#pragma unroll
    for (int mt = 0; mt < 2; mt++)
#pragma unroll
        for (int i2 = 0; i2 < 2; i2++) {
            int r = row0 + wm*32 + mt*16 + qg + i2*8;
            float c0v = coords[(size_t)r*2], c1v = coords[(size_t)r*2 + 1];
#pragma unroll
            for (int nt = 0; nt < 8; nt++)
#pragma unroll
                for (int j = 0; j < 2; j++) {
                    int c = col0 + wn*64 + nt*8 + rg*2 + j;
                    float v = acc[mt][nt][i2*2 + j] + b1[c] + c0v*aW[c] + c1v*aW[256 + c] + ab[c];
                    v = fmaxf(v, 0.f);
                    acc[mt][nt][i2*2 + j] = v;
                    sums[mt][i2] += v;
                    sqs[mt][i2]  += v * v;
                }
        }
    if (col0 == 0) {
#pragma unroll
        for (int mt = 0; mt < 2; mt++)
#pragma unroll
            for (int i2 = 0; i2 < 2; i2++) {
                int r = row0 + wm*32 + mt*16 + qg + i2*8;
#pragma unroll
                for (int nt = 0; nt < 8; nt++)
#pragma unroll
                    for (int j = 0; j < 2; j++) {
                        int c = wn*64 + nt*8 + rg*2 + j;
                        u[(size_t)r*128 + c] = acc[mt][nt][i2*2 + j];
                    }
            }
    } else {
        float* rowstat = (float*)As;   // reuse smem: [128][4]
        __syncthreads();
#pragma unroll
        for (int mt = 0; mt < 2; mt++)
#pragma unroll
            for (int i2 = 0; i2 < 2; i2++) {
                float s = sums[mt][i2], q = sqs[mt][i2];
                s += __shfl_xor_sync(0xffffffffu, s, 1);
                s += __shfl_xor_sync(0xffffffffu, s, 2);
                q += __shfl_xor_sync(0xffffffffu, q, 1);
                q += __shfl_xor_sync(0xffffffffu, q, 2);
                if (rg == 0) {
                    int rl = wm*32 + mt*16 + qg + i2*8;
                    rowstat[rl*4 + wn*2 + 0] = s;
                    rowstat[rl*4 + wn*2 + 1] = q;
                }
            }
        __syncthreads();
#pragma unroll
        for (int mt = 0; mt < 2; mt++)
#pragma unroll
            for (int i2 = 0; i2 < 2; i2++) {
                int rl = wm*32 + mt*16 + qg + i2*8;
                int r = row0 + rl;
                float s = rowstat[rl*4] + rowstat[rl*4 + 2];
                float q = rowstat[rl*4 + 1] + rowstat[rl*4 + 3];
                float mean = s * (1.f/128.f);
                float var  = q * (1.f/128.f) - mean * mean;
                float rinv = rsqrtf(var + 1e-5f);
                int bt = r / NN, node = r - bt * NN;
#pragma unroll
                for (int nt = 0; nt < 8; nt++)
#pragma unroll
                    for (int j = 0; j < 2; j++) {
                        int f = wn*64 + nt*8 + rg*2 + j;
                        float v = (acc[mt][nt][i2*2 + j] - mean) * rinv * sgu_g[f] + sgu_b[f];
                        vnT[((size_t)bt*130 + f + 1)*384 + node] = __float2half_rn(v);
                    }
            }
    }
}

// ---------------- flash attention: grid (3, BT); warp owns 16 q-rows ----
__global__ __launch_bounds__(256)
void attn_kernel(const __half* __restrict__ qkvh, __half* __restrict__ attnout)
{
    extern __shared__ unsigned sm[];
    unsigned* qs = sm;              // [128][68] q rows (feat)
    unsigned* ks = sm + 128*68;     // [64][68] k rows
    unsigned* vs = ks + 64*68;      // [64][68] v rows
    unsigned* Pb = vs + 64*68;      // [128][36] P (key cols, halves)
    const int bt = blockIdx.y, q0 = blockIdx.x * 128;
    const int tid = threadIdx.x;
    const __half* base = qkvh + (size_t)bt * NN * 384;

#pragma unroll
    for (int i = 0; i < 8; i++) {
        int lin = tid + 256*i; int r = lin >> 4, ch = lin & 15;
        int gr = min(q0 + r, NN - 1); bool p = (q0 + r) < NN;
        cp16(sptr(qs + r*68 + ch*4), base + (size_t)gr*384 + ch*8, p);
    }
#define LKV(c0) do {                                                         \
        _Pragma("unroll")                                                    \
        for (int i = 0; i < 4; i++) {                                        \
            int lin = tid + 256*i; int r = lin >> 4, ch = lin & 15;          \
            int gr = min((c0) + r, NN - 1); bool p = ((c0) + r) < NN;        \
            cp16(sptr(ks + r*68 + ch*4), base + (size_t)gr*384 + 128 + ch*8, p); \
            cp16(sptr(vs + r*68 + ch*4), base + (size_t)gr*384 + 256 + ch*8, p); \
        }                                                                    \
    } while (0)
    LKV(0);
    CP_COMMIT(); CP_WAIT0(); __syncthreads();

    const int lane = tid & 31, wid = tid >> 5;
    const int qg = lane >> 2, rg = lane & 3;
    const int R = wid * 16;              // this warp's q-row base
    float Oacc[16][4];
#pragma unroll
    for (int a_=0;a_<16;a_++)
#pragma unroll
        for (int c_=0;c_<4;c_++) Oacc[a_][c_] = 0.f;
    float lacc[2] = {0.f, 0.f};

    const unsigned qaddr  = sptr(qs + (R + (lane & 15))*68 + ((lane >> 4) << 2));
    const unsigned paddrA = sptr(Pb + (R + (lane & 15))*36 + ((lane >> 4) << 2));
    unsigned kaddr[4], vaddr[8];
#pragma unroll
    for (int p = 0; p < 4; p++)
        kaddr[p] = sptr(ks + (p*16 + (lane & 7) + ((lane >> 4) << 3))*68 + (((lane >> 3) & 1) << 2));
#pragma unroll
    for (int p = 0; p < 8; p++)
        vaddr[p] = sptr(vs + ((lane & 7) + ((lane & 8) ? 8 : 0))*68 + p*8 + ((lane >> 4) << 2));

    for (int it = 0; it < 6; it++) {
        const int c0 = it * 64;
        float S[8][4];
#pragma unroll
        for (int a_=0;a_<8;a_++)
#pragma unroll
            for (int c_=0;c_<4;c_++) S[a_][c_] = 0.f;
        // S = q @ k^T over 128 feats
#pragma unroll
        for (int s = 0; s < 8; s++) {
            unsigned a[4], b[4];
            ldsm4(a, qaddr + s*32);
#pragma unroll
            for (int p = 0; p < 4; p++) {
                ldsm4(b, kaddr[p] + s*32);
                mma_f16(S[2*p],     a, b[0], b[1]);
                mma_f16(S[2*p + 1], a, b[2], b[3]);
            }
        }
        // exp + mask + store P + per-thread row sums
        float rs[2] = {0.f, 0.f};
#pragma unroll
        for (int ntl = 0; ntl < 8; ntl++)
#pragma unroll
            for (int i2 = 0; i2 < 2; i2++) {
                int colb = c0 + ntl*8 + rg*2;
                float p0 = (colb     < NN) ? __expf(S[ntl][i2*2])     : 0.f;
                float p1 = (colb + 1 < NN) ? __expf(S[ntl][i2*2 + 1]) : 0.f;
                __half2 hp = __floats2half2_rn(p0, p1);
                rs[i2] += __half2float(__low2half(hp)) + __half2float(__high2half(hp));
                Pb[(R + qg + i2*8)*36 + ntl*4 + rg] = h2u(hp);
            }
#pragma unroll
        for (int i2 = 0; i2 < 2; i2++) {
            rs[i2] += __shfl_xor_sync(0xffffffffu, rs[i2], 1);
            rs[i2] += __shfl_xor_sync(0xffffffffu, rs[i2], 2);
            lacc[i2] += rs[i2];
        }
        __syncwarp();
        // O += P @ v  (V via ldmatrix.trans)
#pragma unroll
        for (int s = 0; s < 4; s++) {
            unsigned a[4], b[4];
            ldsm4(a, paddrA + s*32);
#pragma unroll
            for (int p = 0; p < 8; p++) {
                ldsm4t(b, vaddr[p] + s*(16*68*4));
                mma_f16(Oacc[2*p],     a, b[0], b[1]);
                mma_f16(Oacc[2*p + 1], a, b[2], b[3]);
            }
        }
        __syncthreads();
        if (it < 5) {
            LKV((it + 1) * 64);
            CP_COMMIT(); CP_WAIT0(); __syncthreads();
        }
    }
#undef LKV
#pragma unroll
    for (int i2 = 0; i2 < 2; i2++) {
        int n = q0 + R + qg + i2*8;
        if (n >= NN) continue;
        float inv = 1.f / lacc[i2];
        __half* orow = attnout + ((size_t)bt * NN + n) * 128;
#pragma unroll
        for (int ng = 0; ng < 16; ng++) {
            int f = ng*8 + rg*2;
            *(__half2*)(orow + f) =
                __floats2half2_rn(Oacc[ng][i2*2] * inv, Oacc[ng][i2*2 + 1] * inv);
        }
    }
}

// ---------------- conv: A=cwt[tap][n][m], B=vnT rows (tap = row shift) --
__global__ __launch_bounds__(256)
void conv_tc(const __half* __restrict__ cwt, const __half* __restrict__ vnT,
             const float* __restrict__ cb, const float* __restrict__ gres,
             const float* __restrict__ u, __half* __restrict__ sg)
{
    extern __shared__ unsigned sm[];
    unsigned* As = sm;             // [128][68]  cwt rows n, cols m-chunk
    unsigned* Bs = sm + 128*68;    // [130][68]  vnT rows f(+1), cols m-chunk
    const int bt = blockIdx.y, n0 = blockIdx.x * 128;
    const int tid = threadIdx.x;
    const __half* vb = vnT + (size_t)bt * 130 * 384;
    WARP_DECLS
    ACC_DECL

    unsigned aaddr[2], baddr[4];
#pragma unroll
    for (int mt = 0; mt < 2; mt++)
        aaddr[mt] = sptr(As + (wm*32 + mt*16 + (lane & 15))*68 + ((lane >> 4) << 2));
#pragma unroll
    for (int p = 0; p < 4; p++)
        baddr[p] = sptr(Bs + (wn*64 + p*16 + (lane & 7) + ((lane >> 4) << 3))*68 + (((lane >> 3) & 1) << 2));

    for (int mc = 0; mc < 3; mc++) {
        for (int tap = 0; tap < 3; tap++) {
            if (mc || tap) __syncthreads();
            if (tap == 0) {
#pragma unroll
                for (int i = 0; i < 9; i++) {
                    int lin = tid + 256*i;
                    if (lin < 2080) {
                        int r = lin >> 4, ch = lin & 15;
                        cp16(sptr(Bs + r*68 + ch*4),
                             vb + (size_t)r*384 + mc*128 + ch*8, true);
                    }
                }
            }
#pragma unroll
            for (int i = 0; i < 8; i++) {
                int lin = tid + 256*i; int r = lin >> 4, ch = lin & 15;
                cp16(sptr(As + r*68 + ch*4),
                     cwt + ((size_t)tap*384 + n0 + r)*384 + mc*128 + ch*8, true);
            }
            CP_COMMIT(); CP_WAIT0(); __syncthreads();
            const int toff = tap * 272;   // tap rows of Bs in bytes (68*4)
#pragma unroll
            for (int s = 0; s < 8; s++) {
                unsigned a[2][4], b[4][4];
#pragma unroll
                for (int mt = 0; mt < 2; mt++) ldsm4(a[mt], aaddr[mt] + s*32);
#pragma unroll
                for (int p = 0; p < 4; p++) ldsm4(b[p], baddr[p] + toff + s*32);
#pragma unroll
                for (int mt = 0; mt < 2; mt++)
#pragma unroll
                    for (int p = 0; p < 4; p++) {
                        mma_f16(acc[mt][2*p],     a[mt], b[p][0], b[p][1]);
                        mma_f16(acc[mt][2*p + 1], a[mt], b[p][2], b[p][3]);
                    }
            }
        }
    }
#pragma unroll
    for (int mt = 0; mt < 2; mt++)
#pragma unroll
        for (int i2 = 0; i2 < 2; i2++) {
            int n = n0 + wm*32 + mt*16 + qg + i2*8;
            if (n >= NN) continue;
            size_t row = (size_t)bt * NN + n;
            float bias = cb[n];
#pragma unroll
            for (int nt = 0; nt < 8; nt++) {
                int f = wn*64 + nt*8 + rg*2;
                float v0 = (acc[mt][nt][i2*2]     + bias + gres[row*128 + f])     * u[row*128 + f];
                float v1 = (acc[mt][nt][i2*2 + 1] + bias + gres[row*128 + f + 1]) * u[row*128 + f + 1];
                *(__half2*)(sg + row*128 + f) = __floats2half2_rn(v0, v1);
            }
        }
}

// ---------------- host launcher ----------------
extern "C" void kernel_launch(void* const* d_in, const int* in_sizes, int n_in,
                              void* d_out, int out_size)
{
    const float* x      = (const float*)d_in[0];
    const float* norm_g = (const float*)d_in[1];
    const float* norm_b = (const float*)d_in[2];
    const float* W1     = (const float*)d_in[3];
    const float* b1     = (const float*)d_in[4];
    const float* aff1_W = (const float*)d_in[5];
    const float* aff1_b = (const float*)d_in[6];
    const float* Wl     = (const float*)d_in[7];
    const float* bl     = (const float*)d_in[8];
    const float* sgu_g  = (const float*)d_in[9];
    const float* sgu_b  = (const float*)d_in[10];
    const float* conv_w = (const float*)d_in[11];
    const float* conv_b = (const float*)d_in[12];
    const float* Wqkv   = (const float*)d_in[13];
    const float* bqkv   = (const float*)d_in[14];
    const float* Wo     = (const float*)d_in[15];
    const float* bo     = (const float*)d_in[16];
    const float* W2     = (const float*)d_in[17];
    const float* b2     = (const float*)d_in[18];
    float* out = (float*)d_out;

    __half *xn, *qkvh, *vnT, *attnout, *sg, *wqkv, *w1, *wo, *w2, *cwt;
    float *coords, *uu, *gateres;
    cudaGetSymbolAddress((void**)&xn,      g_xn);
    cudaGetSymbolAddress((void**)&qkvh,    g_qkvh);
    cudaGetSymbolAddress((void**)&coords,  g_coords);
    cudaGetSymbolAddress((void**)&uu,      g_u);
    cudaGetSymbolAddress((void**)&vnT,     g_vnT);
    cudaGetSymbolAddress((void**)&attnout, g_attnout);
    cudaGetSymbolAddress((void**)&gateres, g_gateres);
    cudaGetSymbolAddress((void**)&sg,      g_sg);
    cudaGetSymbolAddress((void**)&wqkv,    g_wqkv);
    cudaGetSymbolAddress((void**)&w1,      g_w1);
    cudaGetSymbolAddress((void**)&wo,      g_wo);
    cudaGetSymbolAddress((void**)&w2,      g_w2);
    cudaGetSymbolAddress((void**)&cwt,     g_cwt);

    const int GEMM_SMEM = (2*128*68) * 4;                       // 69632
    const int ATTN_SMEM = (128*68 + 2*64*68 + 128*36) * 4;      // 88064
    const int CONV_SMEM = (128*68 + 130*68) * 4;                // 70176
    static bool attr_done = false;
    if (!attr_done) {
        cudaFuncSetAttribute(gemm_h<0>,   cudaFuncAttributeMaxDynamicSharedMemorySize, GEMM_SMEM);
        cudaFuncSetAttribute(gemm_h<1>,   cudaFuncAttributeMaxDynamicSharedMemorySize, GEMM_SMEM);
        cudaFuncSetAttribute(gemm_h<2>,   cudaFuncAttributeMaxDynamicSharedMemorySize, GEMM_SMEM);
        cudaFuncSetAttribute(fc1_kernel,  cudaFuncAttributeMaxDynamicSharedMemorySize, GEMM_SMEM);
        cudaFuncSetAttribute(attn_kernel, cudaFuncAttributeMaxDynamicSharedMemorySize, ATTN_SMEM);
        cudaFuncSetAttribute(conv_tc,     cudaFuncAttributeMaxDynamicSharedMemorySize, CONV_SMEM);
        attr_done = true;
    }

    // 0) weights -> half (transposed / padded)
    prep_kernel<<<1687, 256>>>(Wqkv, W1, Wo, W2, conv_w, wqkv, w1, wo, w2, cwt);
    // 1) LN(x) -> xn half + coords
    ln_kernel<<<(MT + 7) / 8, 256>>>(x, xn, norm_g, norm_b, coords, Wl, bl);
    // 2) qkv = xn @ Wqkv + bqkv -> qkvh half [row][384]
    {
        dim3 g(3, 975);
        gemm_h<0><<<g, 256, GEMM_SMEM>>>(xn, wqkv, qkvh, bqkv, nullptr);
    }
    // 3) FC1 + fused SGU-LN -> u (float), vnT (half, transposed)
    {
        dim3 g(2, 975);
        fc1_kernel<<<g, 256, GEMM_SMEM>>>(xn, w1, uu, vnT, coords,
                                          b1, aff1_W, aff1_b, sgu_g, sgu_b);
    }
    // 4) fused attention -> attnout (half)
    {
        dim3 g(3, BT);
        attn_kernel<<<g, 256, ATTN_SMEM>>>(qkvh, attnout);
    }
    // 5) gate_res = attnout @ Wo + bo (float)
    {
        dim3 g(1, 975);
        gemm_h<1><<<g, 256, GEMM_SMEM>>>(attnout, wo, gateres, bo, nullptr);
    }
    // 6) conv + gate -> sg (half)
    {
        dim3 g(3, BT);
        conv_tc<<<g, 256, CONV_SMEM>>>(cwt, vnT, conv_b, gateres, uu, sg);
    }
    // 7) out = relu(sg @ W2 + b2) + x
    {
        dim3 g(1, 975);
        gemm_h<2><<<g, 256, GEMM_SMEM>>>(sg, w2, out, b2, x);
    }
}